// round 11
// baseline (speedup 1.0000x reference)
#include <cuda_runtime.h>
#include <cstdint>

// ---------------------------------------------------------------------------
// Problem constants
// ---------------------------------------------------------------------------
#define BB 4
#define HH 224
#define WW 224
#define HW (HH * WW)                 // 50176
#define NPLANE 128                   // B*C
#define NTOT ((size_t)NPLANE * HW)   // 6,422,528 floats

#define ST 4                     // steps per group
#define NS 3                     // ring slots
#define NGRP (HH / ST)           // 56 groups
#define ABYTES 3584              // bytes per array within a stage (896 floats)
#define STAGEB (4 * ABYTES)      // stage bytes = 14336 (raw) == norm bytes
#define BOUNCE_OFF (NS * STAGEB) // 43008
#define SMEM_BYTES (BOUNCE_OFF + ST * 224 * 4)  // + bounce 3584 = 46592

// Scratch (no cudaMalloc allowed)
__device__ __align__(256) float g_x[NTOT];
__device__ __align__(256) float g_dir[4 * NTOT];

// ---------------------------------------------------------------------------
// PTX helpers
// ---------------------------------------------------------------------------
__device__ __forceinline__ uint32_t s2u(const void* p) {
    return (uint32_t)__cvta_generic_to_shared(p);
}
__device__ __forceinline__ void cpa16(uint32_t dst, const float* src) {
    asm volatile("cp.async.cg.shared.global [%0], [%1], 16;" ::"r"(dst),
                 "l"(src));
}
__device__ __forceinline__ void cpa_commit() {
    asm volatile("cp.async.commit_group;");
}
__device__ __forceinline__ void cpa_waitN() {
    asm volatile("cp.async.wait_group %0;" ::"n"(NS - 1));
}
__device__ __forceinline__ void bar_sync(int id, int n) {
    asm volatile("bar.sync %0, %1;" ::"r"(id), "r"(n) : "memory");
}
__device__ __forceinline__ void bar_arrive(int id, int n) {
    asm volatile("bar.arrive %0, %1;" ::"r"(id), "r"(n) : "memory");
}
// 16B-chunk XOR swizzle (bank decorrelation); flips only bits 6:4.
__device__ __forceinline__ uint32_t swz(uint32_t byte_off) {
    return byte_off ^ ((byte_off >> 3) & 0x70);
}

// ---------------------------------------------------------------------------
// K0: conv2d 3x3 same, 2 -> 32, writes g_x
// ---------------------------------------------------------------------------
__global__ void conv_in_kernel(const float* __restrict__ y,
                               const float* __restrict__ w3) {
    __shared__ float ws[576];
    for (int i = threadIdx.x; i < 576; i += blockDim.x) ws[i] = w3[i];
    __syncthreads();

    int idx = blockIdx.x * blockDim.x + threadIdx.x;
    if (idx >= BB * HW) return;
    int b = idx / HW, pix = idx - b * HW;
    int py = pix / WW, px = pix - py * WW;

    float in[2][3][3];
#pragma unroll
    for (int ic = 0; ic < 2; ic++)
#pragma unroll
        for (int ky = 0; ky < 3; ky++)
#pragma unroll
            for (int kx = 0; kx < 3; kx++) {
                int yy = py + ky - 1, xx = px + kx - 1;
                bool v = ((unsigned)yy < HH) && ((unsigned)xx < WW);
                in[ic][ky][kx] =
                    v ? __ldg(y + ((size_t)(b * 2 + ic)) * HW + yy * WW + xx)
                      : 0.0f;
            }

    for (int oc = 0; oc < 32; oc++) {
        float a = 0.0f;
#pragma unroll
        for (int ic = 0; ic < 2; ic++)
#pragma unroll
            for (int k = 0; k < 9; k++)
                a += in[ic][k / 3][k % 3] * ws[(oc * 2 + ic) * 9 + k];
        g_x[((size_t)(b * 32 + oc)) * HW + pix] = a;
    }
}

// ---------------------------------------------------------------------------
// Producer/consumer scan. Block = 160 threads: warps 0-3 producers, warp 4
// consumer. Ring of NS=3 slots; raw (4 arrays x 896 floats) normalized
// IN-PLACE into (a1,a2,a3,cx) float4 per element, consumption-ordered flat
// index f = 224*j + s (j=step-in-group, s=lane).
// Named barriers: 1 = producers-only (128), 2 = norm-full (160),
// 3 = slot-empty (160). Producers ALWAYS sync on 3 each group (consumer
// always arrives) so barrier rounds stay phase-aligned through the tail;
// only the refill itself is conditional.
// ---------------------------------------------------------------------------
template <bool HOR, bool REV>
__device__ void scan_pc(const float* __restrict__ g1,
                        const float* __restrict__ g2,
                        const float* __restrict__ g3,
                        const float* __restrict__ xp, float* __restrict__ yp,
                        char* ring, float* bounce, int tid) {
    const int wid = tid >> 5;

    if (wid < 4) {
        // ---------------- producers ----------------
        const float* arr[4] = {g1, g2, g3, xp};
        const int p = tid;  // 0..127

        auto fill = [&](int slot, int tg) {
            uint32_t sb = s2u(ring) + (uint32_t)(slot * STAGEB);
            int base = REV ? 220 - 4 * tg : 4 * tg;
#pragma unroll
            for (int i = 0; i < 7; i++) {
                int C = p + 128 * i;               // flat chunk id, 0..895
                int a = C / 224, r = C - 224 * a;  // array, chunk-in-array
                const float* src;
                if (HOR) {
                    src = arr[a] + (size_t)r * WW + base;
                } else {
                    int j = r / 56, q = r - 56 * j;
                    int row = REV ? 223 - (4 * tg + j) : 4 * tg + j;
                    src = arr[a] + (size_t)row * WW + q * 4;
                }
                cpa16(sb + (uint32_t)(a * ABYTES) + swz((uint32_t)(16 * r)),
                      src);
            }
            cpa_commit();
        };

        fill(0, 0);
        fill(1, 1);
        fill(2, 2);

        for (int tg = 0; tg < NGRP; tg++) {
            int slot = tg % NS;
            char* sp = ring + slot * STAGEB;
            cpa_waitN();
            bar_sync(1, 128);  // all fills of this slot visible

            // Read raw (my 7 elements, 4 arrays each) into registers.
            float G[7][4];
#pragma unroll
            for (int i = 0; i < 7; i++) {
                int f = p + 128 * i;  // 0..895
                int j = f / 224, s = f - 224 * j;
#pragma unroll
                for (int a = 0; a < 4; a++) {
                    uint32_t off;
                    if (HOR) {
                        int cR = REV ? 3 - j : j;  // column within 16B chunk
                        off = (uint32_t)(a * ABYTES) +
                              swz((uint32_t)(16 * s)) + 4 * cR;
                    } else {
                        off = (uint32_t)(a * ABYTES) +
                              swz((uint32_t)(16 * (f >> 2))) + 4 * (f & 3);
                    }
                    G[i][a] = *(const float*)(sp + off);
                }
            }
            bar_sync(1, 128);  // all raw reads done -> safe to overwrite

            // Normalize and write norm float4 in-place (consumption order).
#pragma unroll
            for (int i = 0; i < 7; i++) {
                int f = p + 128 * i;
                float sa = fabsf(G[i][0]) + fabsf(G[i][1]) + fabsf(G[i][2]);
                float inv = __fdividef(1.0f, fmaxf(sa, 1.0f));
                float a1 = G[i][0] * inv;
                float a2 = G[i][1] * inv;
                float a3 = G[i][2] * inv;
                float cx = (1.0f - a1 - a2 - a3) * G[i][3];
                *(float4*)(sp + swz((uint32_t)(16 * f))) =
                    make_float4(a1, a2, a3, cx);
            }
            bar_arrive(2, 160);  // norm[tg] ready

            bar_sync(3, 160);  // consumer finished this slot's chain
            if (tg + NS < NGRP) fill(slot, tg + NS);
        }
    } else {
        // ---------------- consumer ----------------
        const int t = tid - 128;  // 0..31, owns lanes 7t..7t+6
        float h[7];
#pragma unroll
        for (int k = 0; k < 7; k++) h[k] = 0.0f;

        for (int tg = 0; tg < NGRP; tg++) {
            int slot = tg % NS;
            char* sp = ring + slot * STAGEB;
            bar_sync(2, 160);  // norm[tg] ready

            float hv[ST][7];
#pragma unroll
            for (int j = 0; j < ST; j++) {
                float4 q[7];
#pragma unroll
                for (int k = 0; k < 7; k++)
                    q[k] = *(const float4*)(sp +
                                            swz((uint32_t)(16 * (224 * j +
                                                                 7 * t + k))));
                float hl = __shfl_up_sync(0xffffffffu, h[6], 1);
                float hr = __shfl_down_sync(0xffffffffu, h[0], 1);
                if (t == 0) hl = 0.0f;
                if (t == 31) hr = 0.0f;

                float hn[7];
#pragma unroll
                for (int k = 0; k < 7; k++) {
                    float l = (k == 0) ? hl : h[k - 1];
                    float r = (k == 6) ? hr : h[k + 1];
                    hn[k] = fmaf(q[k].x, l,
                                 fmaf(q[k].y, h[k], fmaf(q[k].z, r, q[k].w)));
                }
#pragma unroll
                for (int k = 0; k < 7; k++) {
                    h[k] = hn[k];
                    hv[j][k] = hn[k];
                }
            }
            bar_arrive(3, 160);  // chain consumed all q -> slot reusable

            if (!HOR) {
                // Bounce through smem for coalesced global stores.
#pragma unroll
                for (int j = 0; j < ST; j++)
#pragma unroll
                    for (int k = 0; k < 7; k++)
                        bounce[j * 224 + 7 * t + k] = hv[j][k];
                __syncwarp();
#pragma unroll
                for (int j = 0; j < ST; j++) {
                    int row = REV ? 223 - (4 * tg + j) : 4 * tg + j;
#pragma unroll
                    for (int m = 0; m < 7; m++)
                        yp[(size_t)row * WW + t + 32 * m] =
                            bounce[j * 224 + t + 32 * m];
                }
                __syncwarp();
            } else {
                int base = REV ? 220 - 4 * tg : 4 * tg;
#pragma unroll
                for (int k = 0; k < 7; k++) {
                    float4 o;
                    if (REV) {
                        o.x = hv[3][k]; o.y = hv[2][k];
                        o.z = hv[1][k]; o.w = hv[0][k];
                    } else {
                        o.x = hv[0][k]; o.y = hv[1][k];
                        o.z = hv[2][k]; o.w = hv[3][k];
                    }
                    *(float4*)(yp + (size_t)(7 * t + k) * WW + base) = o;
                }
            }
        }
    }
}

// ---------------------------------------------------------------------------
// Scan kernel: grid (128 planes, 4 directions), block = 160 threads.
// d: 0=lr (W fwd), 1=rl (H rev), 2=du (H fwd), 3=ud (W rev);
// direction d uses gate channel groups 3d..3d+2 (matches reference).
// ---------------------------------------------------------------------------
__global__ void __launch_bounds__(160, 4) scan_kernel(
    const float* __restrict__ gates) {
    extern __shared__ __align__(128) char smem[];

    int tid = threadIdx.x;
    int plane = blockIdx.x;
    int d = blockIdx.y;
    int b = plane >> 5, c = plane & 31;

    const float* g1 = gates + ((size_t)(b * 384 + (3 * d + 0) * 32 + c)) * HW;
    const float* g2 = gates + ((size_t)(b * 384 + (3 * d + 1) * 32 + c)) * HW;
    const float* g3 = gates + ((size_t)(b * 384 + (3 * d + 2) * 32 + c)) * HW;
    const float* xp = g_x + (size_t)plane * HW;
    float* yp = g_dir + (size_t)d * NTOT + (size_t)plane * HW;

    float* bounce = (float*)(smem + BOUNCE_OFF);

    switch (d) {
        case 0:  scan_pc<true,  false>(g1, g2, g3, xp, yp, smem, bounce, tid); break;
        case 1:  scan_pc<false, true >(g1, g2, g3, xp, yp, smem, bounce, tid); break;
        case 2:  scan_pc<false, false>(g1, g2, g3, xp, yp, smem, bounce, tid); break;
        default: scan_pc<true,  true >(g1, g2, g3, xp, yp, smem, bounce, tid); break;
    }
}

// ---------------------------------------------------------------------------
// Combine: g_x = elementwise max over the 4 direction buffers (float4).
// ---------------------------------------------------------------------------
__global__ void combine_kernel() {
    const size_t n4 = NTOT / 4;
    const float4* p0 = (const float4*)g_dir;
    const float4* p1 = (const float4*)(g_dir + NTOT);
    const float4* p2 = (const float4*)(g_dir + 2 * NTOT);
    const float4* p3 = (const float4*)(g_dir + 3 * NTOT);
    float4* o = (float4*)g_x;
    for (size_t i = blockIdx.x * (size_t)blockDim.x + threadIdx.x; i < n4;
         i += (size_t)gridDim.x * blockDim.x) {
        float4 a = __ldg(p0 + i), b = __ldg(p1 + i);
        float4 c = __ldg(p2 + i), d = __ldg(p3 + i);
        float4 r;
        r.x = fmaxf(fmaxf(a.x, b.x), fmaxf(c.x, d.x));
        r.y = fmaxf(fmaxf(a.y, b.y), fmaxf(c.y, d.y));
        r.z = fmaxf(fmaxf(a.z, b.z), fmaxf(c.z, d.z));
        r.w = fmaxf(fmaxf(a.w, b.w), fmaxf(c.w, d.w));
        o[i] = r;
    }
}

// ---------------------------------------------------------------------------
// K3: conv2d 3x3 same 32 -> 2 on g_x, fused log_softmax over the 2 channels.
// ---------------------------------------------------------------------------
__global__ void conv_out_kernel(const float* __restrict__ w4,
                                float* __restrict__ out) {
    __shared__ float ws[576];
    for (int i = threadIdx.x; i < 576; i += blockDim.x) ws[i] = w4[i];
    __syncthreads();

    int idx = blockIdx.x * blockDim.x + threadIdx.x;
    if (idx >= BB * HW) return;
    int b = idx / HW, pix = idx - b * HW;
    int py = pix / WW, px = pix - py * WW;

    float a0 = 0.0f, a1 = 0.0f;
    for (int ic = 0; ic < 32; ic++) {
        const float* ip = g_x + ((size_t)(b * 32 + ic)) * HW;
#pragma unroll
        for (int ky = 0; ky < 3; ky++) {
            int yy = py + ky - 1;
            bool vy = (unsigned)yy < HH;
#pragma unroll
            for (int kx = 0; kx < 3; kx++) {
                int xx = px + kx - 1;
                float v = (vy && (unsigned)xx < WW)
                              ? __ldg(ip + yy * WW + xx)
                              : 0.0f;
                int wi = ic * 9 + ky * 3 + kx;
                a0 += v * ws[wi];
                a1 += v * ws[288 + wi];
            }
        }
    }
    float m = fmaxf(a0, a1);
    float l = m + logf(expf(a0 - m) + expf(a1 - m));
    out[(size_t)(b * 2) * HW + pix] = a0 - l;
    out[(size_t)(b * 2 + 1) * HW + pix] = a1 - l;
}

// ---------------------------------------------------------------------------
// Launch: K0 -> scan(pass1) -> combine -> scan(pass2) -> combine -> K3
// ---------------------------------------------------------------------------
extern "C" void kernel_launch(void* const* d_in, const int* in_sizes, int n_in,
                              void* d_out, int out_size) {
    const float* gates = (const float*)d_in[0];
    const float* y     = (const float*)d_in[1];
    const float* w3    = (const float*)d_in[2];
    const float* w4    = (const float*)d_in[3];
    float* out = (float*)d_out;

    int pxblocks = (BB * HW + 255) / 256;
    dim3 sg(NPLANE, 4);

    conv_in_kernel<<<pxblocks, 256>>>(y, w3);
    scan_kernel<<<sg, 160, SMEM_BYTES>>>(gates);
    combine_kernel<<<2048, 256>>>();
    scan_kernel<<<sg, 160, SMEM_BYTES>>>(gates);
    combine_kernel<<<2048, 256>>>();
    conv_out_kernel<<<pxblocks, 256>>>(w4, out);
}

// round 12
// speedup vs baseline: 2.2001x; 2.2001x over previous
#include <cuda_runtime.h>
#include <cstdint>

// ---------------------------------------------------------------------------
// Problem constants
// ---------------------------------------------------------------------------
#define BB 4
#define HH 224
#define WW 224
#define HW (HH * WW)                 // 50176
#define NPLANE 128                   // B*C
#define NTOT ((size_t)NPLANE * HW)   // 6,422,528 floats
#define NGT 768                      // transposed gate planes (2 dirs x 3 x 128)

#define ST 4                     // steps per pipeline stage
#define NS 3                     // pipeline stages
#define NGRP (HH / ST)           // 56 groups

// Scratch (no cudaMalloc allowed)
__device__ __align__(256) float g_x[NTOT];
__device__ __align__(256) float g_xt[NTOT];          // transposed x
__device__ __align__(256) float g_dir[4 * NTOT];     // d0,d3 stored transposed
__device__ __align__(256) float g_gt[(size_t)NGT * HW];  // transposed gates

// ---------------------------------------------------------------------------
// cp.async helpers
// ---------------------------------------------------------------------------
__device__ __forceinline__ uint32_t s2u(const void* p) {
    return (uint32_t)__cvta_generic_to_shared(p);
}
__device__ __forceinline__ void cpa16(float* dst, const float* src) {
    asm volatile("cp.async.cg.shared.global [%0], [%1], 16;" ::"r"(s2u(dst)),
                 "l"(src));
}
__device__ __forceinline__ void cpa_commit() {
    asm volatile("cp.async.commit_group;");
}
__device__ __forceinline__ void cpa_waitN() {
    asm volatile("cp.async.wait_group %0;" ::"n"(NS - 1));
}

// ---------------------------------------------------------------------------
// K0: conv2d 3x3 same, 2 -> 32, writes g_x
// ---------------------------------------------------------------------------
__global__ void conv_in_kernel(const float* __restrict__ y,
                               const float* __restrict__ w3) {
    __shared__ float ws[576];
    for (int i = threadIdx.x; i < 576; i += blockDim.x) ws[i] = w3[i];
    __syncthreads();

    int idx = blockIdx.x * blockDim.x + threadIdx.x;
    if (idx >= BB * HW) return;
    int b = idx / HW, pix = idx - b * HW;
    int py = pix / WW, px = pix - py * WW;

    float in[2][3][3];
#pragma unroll
    for (int ic = 0; ic < 2; ic++)
#pragma unroll
        for (int ky = 0; ky < 3; ky++)
#pragma unroll
            for (int kx = 0; kx < 3; kx++) {
                int yy = py + ky - 1, xx = px + kx - 1;
                bool v = ((unsigned)yy < HH) && ((unsigned)xx < WW);
                in[ic][ky][kx] =
                    v ? __ldg(y + ((size_t)(b * 2 + ic)) * HW + yy * WW + xx)
                      : 0.0f;
            }

    for (int oc = 0; oc < 32; oc++) {
        float a = 0.0f;
#pragma unroll
        for (int ic = 0; ic < 2; ic++)
#pragma unroll
            for (int k = 0; k < 9; k++)
                a += in[ic][k / 3][k % 3] * ws[(oc * 2 + ic) * 9 + k];
        g_x[((size_t)(b * 32 + oc)) * HW + pix] = a;
    }
}

// ---------------------------------------------------------------------------
// Tiled 32x32 plane transposes (224 = 7*32, no bounds checks needed).
// ---------------------------------------------------------------------------
__global__ void transpose_x_kernel() {
    __shared__ float t[32][33];
    int plane = blockIdx.z;
    const float* src = g_x + (size_t)plane * HW;
    float* dst = g_xt + (size_t)plane * HW;
    int x0 = blockIdx.x * 32, y0 = blockIdx.y * 32;
#pragma unroll
    for (int dy = threadIdx.y; dy < 32; dy += 8)
        t[dy][threadIdx.x] = src[(y0 + dy) * WW + x0 + threadIdx.x];
    __syncthreads();
#pragma unroll
    for (int dy = threadIdx.y; dy < 32; dy += 8)
        dst[(x0 + dy) * HH + y0 + threadIdx.x] = t[threadIdx.x][dy];
}

// Transpose the 6 W-direction gate channel-groups (d0: groups 0-2,
// d3: groups 9-11) into g_gt[(dh*3+gi)*128 + plane].
__global__ void transpose_gates_kernel(const float* __restrict__ gates) {
    __shared__ float t[32][33];
    int q = blockIdx.z;                   // 0..767 = dh*384 + gi*128 + plane
    int dh = q / 384, rem = q - dh * 384;
    int gi = rem >> 7, plane = rem & 127;
    int b = plane >> 5, c = plane & 31;
    int ch = (dh ? (9 + gi) : gi) * 32 + c;
    const float* src = gates + ((size_t)(b * 384 + ch)) * HW;
    float* dst = g_gt + (size_t)q * HW;
    int x0 = blockIdx.x * 32, y0 = blockIdx.y * 32;
#pragma unroll
    for (int dy = threadIdx.y; dy < 32; dy += 8)
        t[dy][threadIdx.x] = src[(y0 + dy) * WW + x0 + threadIdx.x];
    __syncthreads();
#pragma unroll
    for (int dy = threadIdx.y; dy < 32; dy += 8)
        dst[(x0 + dy) * HH + y0 + threadIdx.x] = t[threadIdx.x][dy];
}

// ---------------------------------------------------------------------------
// Row-coalesced scan (R2 vertical path, now used for ALL directions).
// Thread s = cross-axis lane; serial axis t = rows of the (possibly
// transposed) plane. Stage: sbuf[NS][4][ST*224], [a][j*224+s]; fill is
// 16B-chunk coalesced; consume conflict-free; per-step hbuf double buffer.
// ---------------------------------------------------------------------------
template <bool REV>
__device__ void scan_v(const float* __restrict__ g1,
                       const float* __restrict__ g2,
                       const float* __restrict__ g3,
                       const float* __restrict__ xp, float* __restrict__ yp,
                       float (*sbuf)[4][ST * 224], float (*hbuf)[226], int s) {
    const float* arr[4] = {g1, g2, g3, xp};
    const int jf = s / 56, qf = s - jf * 56;  // fill row-in-group, 16B chunk

    auto fill = [&](int st, int tg) {
        int row = REV ? 223 - (4 * tg + jf) : 4 * tg + jf;
#pragma unroll
        for (int a = 0; a < 4; a++)
            cpa16(&sbuf[st][a][jf * 224 + qf * 4],
                  arr[a] + (size_t)row * WW + qf * 4);
        cpa_commit();
    };

    fill(0, 0);
    fill(1, 1);
    fill(2, 2);

    int cur = 0;
    float hown = 0.0f;

    for (int tg = 0; tg < NGRP; tg++) {
        int st = tg % NS;
        cpa_waitN();
        __syncthreads();

        // Off-chain: normalize gates + premultiply x for all 4 steps.
        float a1[ST], a2[ST], a3[ST], cx[ST];
#pragma unroll
        for (int j = 0; j < ST; j++) {
            float G1 = sbuf[st][0][j * 224 + s];
            float G2 = sbuf[st][1][j * 224 + s];
            float G3 = sbuf[st][2][j * 224 + s];
            float X = sbuf[st][3][j * 224 + s];
            float inv = __fdividef(
                1.0f, fmaxf(fabsf(G1) + fabsf(G2) + fabsf(G3), 1.0f));
            a1[j] = G1 * inv;
            a2[j] = G2 * inv;
            a3[j] = G3 * inv;
            cx[j] = (1.0f - a1[j] - a2[j] - a3[j]) * X;
        }

        // Serial recurrence steps.
#pragma unroll
        for (int j = 0; j < ST; j++) {
            float hl = hbuf[cur][s];      // h_prev[s-1] (halo at 0)
            float hr = hbuf[cur][s + 2];  // h_prev[s+1] (halo at 225)
            float hn =
                fmaf(a1[j], hl, fmaf(a2[j], hown, fmaf(a3[j], hr, cx[j])));
            hbuf[cur ^ 1][s + 1] = hn;
            hown = hn;
            cur ^= 1;
            __syncthreads();
            int row = REV ? 223 - (4 * tg + j) : 4 * tg + j;
            yp[(size_t)row * WW + s] = hn;  // coalesced
        }

        int nt = tg + NS;
        if (nt < NGRP) fill(st, nt);
        else cpa_commit();  // keep wait_group counts aligned in the tail
    }
}

// ---------------------------------------------------------------------------
// Scan kernel: grid (128 planes, 4 directions), 224 threads.
// d0 lr (W fwd)  -> transposed arrays (g_gt dh=0, g_xt), out transposed
// d1 rl (H rev)  -> native gates groups 3-5, g_x
// d2 du (H fwd)  -> native gates groups 6-8, g_x
// d3 ud (W rev)  -> transposed arrays (g_gt dh=1, g_xt), out transposed
// ---------------------------------------------------------------------------
__global__ void __launch_bounds__(224) scan_kernel(
    const float* __restrict__ gates) {
    __shared__ float sbuf[NS][4][ST * 224];  // 43008 B
    __shared__ float hbuf[2][226];

    int s = threadIdx.x;
    int plane = blockIdx.x;
    int d = blockIdx.y;
    int b = plane >> 5, c = plane & 31;

    const float *g1, *g2, *g3, *xp;
    if (d == 1 || d == 2) {
        int grp0 = (d == 1) ? 3 : 6;
        g1 = gates + ((size_t)(b * 384 + (grp0 + 0) * 32 + c)) * HW;
        g2 = gates + ((size_t)(b * 384 + (grp0 + 1) * 32 + c)) * HW;
        g3 = gates + ((size_t)(b * 384 + (grp0 + 2) * 32 + c)) * HW;
        xp = g_x + (size_t)plane * HW;
    } else {
        int dh = (d == 0) ? 0 : 1;
        g1 = g_gt + ((size_t)((dh * 3 + 0) * 128 + plane)) * HW;
        g2 = g_gt + ((size_t)((dh * 3 + 1) * 128 + plane)) * HW;
        g3 = g_gt + ((size_t)((dh * 3 + 2) * 128 + plane)) * HW;
        xp = g_xt + (size_t)plane * HW;
    }
    float* yp = g_dir + (size_t)d * NTOT + (size_t)plane * HW;

    hbuf[0][s + 1] = 0.0f;
    if (s < 2) { hbuf[0][s * 225] = 0.0f; hbuf[1][s * 225] = 0.0f; }
    __syncthreads();

    if (d == 1 || d == 3)
        scan_v<true>(g1, g2, g3, xp, yp, sbuf, hbuf, s);
    else
        scan_v<false>(g1, g2, g3, xp, yp, sbuf, hbuf, s);
}

// ---------------------------------------------------------------------------
// Combine: max over 4 direction buffers; d0,d3 are transposed. Tiled 32x32.
// DUAL: also emit the max in transposed orientation (feeds next pass's g_xt).
// ---------------------------------------------------------------------------
template <bool DUAL>
__global__ void combine_t_kernel() {
    __shared__ float t0[32][33], t3[32][33], m[32][33];
    int plane = blockIdx.z;
    const float* p0t = g_dir + 0 * NTOT + (size_t)plane * HW;
    const float* p1 = g_dir + 1 * NTOT + (size_t)plane * HW;
    const float* p2 = g_dir + 2 * NTOT + (size_t)plane * HW;
    const float* p3t = g_dir + 3 * NTOT + (size_t)plane * HW;
    int x0 = blockIdx.x * 32, y0 = blockIdx.y * 32;
    int tx = threadIdx.x;

#pragma unroll
    for (int dy = threadIdx.y; dy < 32; dy += 8) {
        t0[dy][tx] = p0t[(x0 + dy) * HH + y0 + tx];
        t3[dy][tx] = p3t[(x0 + dy) * HH + y0 + tx];
    }
    __syncthreads();
#pragma unroll
    for (int dy = threadIdx.y; dy < 32; dy += 8) {
        float v1 = p1[(y0 + dy) * WW + x0 + tx];
        float v2 = p2[(y0 + dy) * WW + x0 + tx];
        float v0 = t0[tx][dy];  // = P0[y0+dy][x0+tx]
        float v3 = t3[tx][dy];
        float mx = fmaxf(fmaxf(v0, v3), fmaxf(v1, v2));
        g_x[(size_t)plane * HW + (y0 + dy) * WW + x0 + tx] = mx;
        if (DUAL) m[dy][tx] = mx;
    }
    if (DUAL) {
        __syncthreads();
#pragma unroll
        for (int dy = threadIdx.y; dy < 32; dy += 8)
            g_xt[(size_t)plane * HW + (x0 + dy) * HH + y0 + tx] = m[tx][dy];
    }
}

// ---------------------------------------------------------------------------
// K3: conv2d 3x3 same 32 -> 2 on g_x, fused log_softmax over the 2 channels.
// ---------------------------------------------------------------------------
__global__ void conv_out_kernel(const float* __restrict__ w4,
                                float* __restrict__ out) {
    __shared__ float ws[576];
    for (int i = threadIdx.x; i < 576; i += blockDim.x) ws[i] = w4[i];
    __syncthreads();

    int idx = blockIdx.x * blockDim.x + threadIdx.x;
    if (idx >= BB * HW) return;
    int b = idx / HW, pix = idx - b * HW;
    int py = pix / WW, px = pix - py * WW;

    float a0 = 0.0f, a1 = 0.0f;
    for (int ic = 0; ic < 32; ic++) {
        const float* ip = g_x + ((size_t)(b * 32 + ic)) * HW;
#pragma unroll
        for (int ky = 0; ky < 3; ky++) {
            int yy = py + ky - 1;
            bool vy = (unsigned)yy < HH;
#pragma unroll
            for (int kx = 0; kx < 3; kx++) {
                int xx = px + kx - 1;
                float v = (vy && (unsigned)xx < WW)
                              ? __ldg(ip + yy * WW + xx)
                              : 0.0f;
                int wi = ic * 9 + ky * 3 + kx;
                a0 += v * ws[wi];
                a1 += v * ws[288 + wi];
            }
        }
    }
    float mx = fmaxf(a0, a1);
    float l = mx + logf(expf(a0 - mx) + expf(a1 - mx));
    out[(size_t)(b * 2) * HW + pix] = a0 - l;
    out[(size_t)(b * 2 + 1) * HW + pix] = a1 - l;
}

// ---------------------------------------------------------------------------
// Launch: conv_in -> transpose(x, gates) -> scan1 -> combine(dual) ->
//         scan2 -> combine -> conv_out
// ---------------------------------------------------------------------------
extern "C" void kernel_launch(void* const* d_in, const int* in_sizes, int n_in,
                              void* d_out, int out_size) {
    const float* gates = (const float*)d_in[0];
    const float* y     = (const float*)d_in[1];
    const float* w3    = (const float*)d_in[2];
    const float* w4    = (const float*)d_in[3];
    float* out = (float*)d_out;

    int pxblocks = (BB * HW + 255) / 256;
    dim3 sg(NPLANE, 4);
    dim3 tb(32, 8);
    dim3 tgx(7, 7, NPLANE);
    dim3 tgg(7, 7, NGT);

    conv_in_kernel<<<pxblocks, 256>>>(y, w3);
    transpose_x_kernel<<<tgx, tb>>>();
    transpose_gates_kernel<<<tgg, tb>>>(gates);
    scan_kernel<<<sg, 224>>>(gates);
    combine_t_kernel<true><<<tgx, tb>>>();
    scan_kernel<<<sg, 224>>>(gates);
    combine_t_kernel<false><<<tgx, tb>>>();
    conv_out_kernel<<<pxblocks, 256>>>(w4, out);
}

// round 13
// speedup vs baseline: 2.8892x; 1.3132x over previous
#include <cuda_runtime.h>
#include <cstdint>

// ---------------------------------------------------------------------------
// Problem constants
// ---------------------------------------------------------------------------
#define BB 4
#define HH 224
#define WW 224
#define HW (HH * WW)                 // 50176
#define NPLANE 128                   // B*C
#define NTOT ((size_t)NPLANE * HW)   // 6,422,528 floats

// vertical scan pipeline (R12 proven path)
#define ST 4
#define NS 3
#define NGRP (HH / ST)               // 56

// horizontal scan slab pipeline
#define STH 32                       // steps per stage (128B per row per array)
#define NSH 2
#define HGRP (WW / STH)              // 7
#define HARR (224 * STH * 4)         // bytes per array per stage = 28672
#define HSTAGEB (4 * HARR)           // 114688
#define HSMEM (NSH * HSTAGEB + 2 * 226 * 4)  // 231184 <= 232448 limit

// Scratch (no cudaMalloc allowed)
__device__ __align__(256) float g_x[NTOT];
__device__ __align__(256) float g_dir[4 * NTOT];  // d0,d3 transposed layout

// ---------------------------------------------------------------------------
// cp.async helpers
// ---------------------------------------------------------------------------
__device__ __forceinline__ uint32_t s2u(const void* p) {
    return (uint32_t)__cvta_generic_to_shared(p);
}
__device__ __forceinline__ void cpa16(uint32_t dst, const float* src) {
    asm volatile("cp.async.cg.shared.global [%0], [%1], 16;" ::"r"(dst),
                 "l"(src));
}
__device__ __forceinline__ void cpa16p(float* dst, const float* src) {
    cpa16(s2u(dst), src);
}
__device__ __forceinline__ void cpa_commit() {
    asm volatile("cp.async.commit_group;");
}
__device__ __forceinline__ void cpa_wait2() {
    asm volatile("cp.async.wait_group 2;");
}
__device__ __forceinline__ void cpa_wait1() {
    asm volatile("cp.async.wait_group 1;");
}

// ---------------------------------------------------------------------------
// K0: conv2d 3x3 same, 2 -> 32, writes g_x
// ---------------------------------------------------------------------------
__global__ void conv_in_kernel(const float* __restrict__ y,
                               const float* __restrict__ w3) {
    __shared__ float ws[576];
    for (int i = threadIdx.x; i < 576; i += blockDim.x) ws[i] = w3[i];
    __syncthreads();

    int idx = blockIdx.x * blockDim.x + threadIdx.x;
    if (idx >= BB * HW) return;
    int b = idx / HW, pix = idx - b * HW;
    int py = pix / WW, px = pix - py * WW;

    float in[2][3][3];
#pragma unroll
    for (int ic = 0; ic < 2; ic++)
#pragma unroll
        for (int ky = 0; ky < 3; ky++)
#pragma unroll
            for (int kx = 0; kx < 3; kx++) {
                int yy = py + ky - 1, xx = px + kx - 1;
                bool v = ((unsigned)yy < HH) && ((unsigned)xx < WW);
                in[ic][ky][kx] =
                    v ? __ldg(y + ((size_t)(b * 2 + ic)) * HW + yy * WW + xx)
                      : 0.0f;
            }

    for (int oc = 0; oc < 32; oc++) {
        float a = 0.0f;
#pragma unroll
        for (int ic = 0; ic < 2; ic++)
#pragma unroll
            for (int k = 0; k < 9; k++)
                a += in[ic][k / 3][k % 3] * ws[(oc * 2 + ic) * 9 + k];
        g_x[((size_t)(b * 32 + oc)) * HW + pix] = a;
    }
}

// ---------------------------------------------------------------------------
// Vertical scan (d1 rl = H reverse, d2 du = H forward). R12 proven path.
// ---------------------------------------------------------------------------
template <bool REV>
__device__ void scan_v_body(const float* __restrict__ g1,
                            const float* __restrict__ g2,
                            const float* __restrict__ g3,
                            const float* __restrict__ xp,
                            float* __restrict__ yp,
                            float (*sbuf)[4][ST * 224], float (*hbuf)[226],
                            int s) {
    const float* arr[4] = {g1, g2, g3, xp};
    const int jf = s / 56, qf = s - jf * 56;

    auto fill = [&](int st, int tg) {
        int row = REV ? 223 - (4 * tg + jf) : 4 * tg + jf;
#pragma unroll
        for (int a = 0; a < 4; a++)
            cpa16p(&sbuf[st][a][jf * 224 + qf * 4],
                   arr[a] + (size_t)row * WW + qf * 4);
        cpa_commit();
    };

    fill(0, 0);
    fill(1, 1);
    fill(2, 2);

    int cur = 0;
    float hown = 0.0f;

    for (int tg = 0; tg < NGRP; tg++) {
        int st = tg % NS;
        cpa_wait2();
        __syncthreads();

        float a1[ST], a2[ST], a3[ST], cx[ST];
#pragma unroll
        for (int j = 0; j < ST; j++) {
            float G1 = sbuf[st][0][j * 224 + s];
            float G2 = sbuf[st][1][j * 224 + s];
            float G3 = sbuf[st][2][j * 224 + s];
            float X = sbuf[st][3][j * 224 + s];
            float inv = __fdividef(
                1.0f, fmaxf(fabsf(G1) + fabsf(G2) + fabsf(G3), 1.0f));
            a1[j] = G1 * inv;
            a2[j] = G2 * inv;
            a3[j] = G3 * inv;
            cx[j] = (1.0f - a1[j] - a2[j] - a3[j]) * X;
        }

#pragma unroll
        for (int j = 0; j < ST; j++) {
            float hl = hbuf[cur][s];
            float hr = hbuf[cur][s + 2];
            float hn =
                fmaf(a1[j], hl, fmaf(a2[j], hown, fmaf(a3[j], hr, cx[j])));
            hbuf[cur ^ 1][s + 1] = hn;
            hown = hn;
            cur ^= 1;
            __syncthreads();
            int row = REV ? 223 - (4 * tg + j) : 4 * tg + j;
            yp[(size_t)row * WW + s] = hn;  // coalesced
        }

        int nt = tg + NS;
        if (nt < NGRP) fill(st, nt);
        else cpa_commit();
    }
}

__global__ void __launch_bounds__(224) scan_v_kernel(
    const float* __restrict__ gates) {
    __shared__ float sbuf[NS][4][ST * 224];
    __shared__ float hbuf[2][226];

    int s = threadIdx.x;
    int plane = blockIdx.x;
    int d = blockIdx.y + 1;  // 1 or 2
    int b = plane >> 5, c = plane & 31;
    int grp0 = (d == 1) ? 3 : 6;

    const float* g1 = gates + ((size_t)(b * 384 + (grp0 + 0) * 32 + c)) * HW;
    const float* g2 = gates + ((size_t)(b * 384 + (grp0 + 1) * 32 + c)) * HW;
    const float* g3 = gates + ((size_t)(b * 384 + (grp0 + 2) * 32 + c)) * HW;
    const float* xp = g_x + (size_t)plane * HW;
    float* yp = g_dir + (size_t)d * NTOT + (size_t)plane * HW;

    hbuf[0][s + 1] = 0.0f;
    if (s < 2) { hbuf[0][s * 225] = 0.0f; hbuf[1][s * 225] = 0.0f; }
    __syncthreads();

    if (d == 1) scan_v_body<true>(g1, g2, g3, xp, yp, sbuf, hbuf, s);
    else        scan_v_body<false>(g1, g2, g3, xp, yp, sbuf, hbuf, s);
}

// ---------------------------------------------------------------------------
// Horizontal scan on NATIVE layout (d0 lr = W forward, d3 ud = W reverse).
// Slab stage: 4 arrays x 224 rows x 32 cols (one 128B line per row per array
// per stage -> full wavefront efficiency). 16B-chunk XOR swizzle c^(row&7)
// makes both fill STS and the stride-128B consume LDS.128 conflict-free.
// Output written in TRANSPOSED orientation (coalesced): yp[col*224 + row].
// ---------------------------------------------------------------------------
template <bool REV>
__device__ void scan_h_body(const float* __restrict__ g1,
                            const float* __restrict__ g2,
                            const float* __restrict__ g3,
                            const float* __restrict__ xp,
                            float* __restrict__ yp, char* slab,
                            float (*hbuf)[226], int s) {
    const float* arr[4] = {g1, g2, g3, xp};

    auto fill = [&](int st, int tg) {
        uint32_t sb = s2u(slab) + (uint32_t)(st * HSTAGEB);
        int base = REV ? 192 - 32 * tg : 32 * tg;  // column base (floats)
#pragma unroll
        for (int i = 0; i < 32; i++) {
            int a = i >> 3;                 // array (compile-time per i)
            int r = (i & 7) * 224 + s;      // chunk-in-array, 0..1791
            int row = r >> 3, ch = r & 7;   // plane row, 16B chunk in row
            cpa16(sb + (uint32_t)(a * HARR + row * 128 +
                                  ((ch ^ (row & 7)) << 4)),
                  arr[a] + (size_t)row * WW + base + ch * 4);
        }
        cpa_commit();
    };

    fill(0, 0);
    fill(1, 1);

    int cur = 0;
    float hown = 0.0f;

    for (int tg = 0; tg < HGRP; tg++) {
        int st = tg & 1;
        cpa_wait1();
        __syncthreads();
        char* sp = slab + st * HSTAGEB;

#pragma unroll
        for (int m = 0; m < 8; m++) {  // 8 chunk-groups of 4 steps
            int cm = REV ? 7 - m : m;
            float4 q[4];
#pragma unroll
            for (int a = 0; a < 4; a++)
                q[a] = *(const float4*)(sp + a * HARR + s * 128 +
                                        ((cm ^ (s & 7)) << 4));

            float a1[4], a2[4], a3[4], cx[4];
#pragma unroll
            for (int j = 0; j < 4; j++) {
                int cc = REV ? 3 - j : j;
                float G1 = ((const float*)&q[0])[cc];
                float G2 = ((const float*)&q[1])[cc];
                float G3 = ((const float*)&q[2])[cc];
                float X = ((const float*)&q[3])[cc];
                float inv = __fdividef(
                    1.0f, fmaxf(fabsf(G1) + fabsf(G2) + fabsf(G3), 1.0f));
                a1[j] = G1 * inv;
                a2[j] = G2 * inv;
                a3[j] = G3 * inv;
                cx[j] = (1.0f - a1[j] - a2[j] - a3[j]) * X;
            }

#pragma unroll
            for (int j = 0; j < 4; j++) {
                float hl = hbuf[cur][s];
                float hr = hbuf[cur][s + 2];
                float hn = fmaf(a1[j], hl,
                                fmaf(a2[j], hown, fmaf(a3[j], hr, cx[j])));
                hbuf[cur ^ 1][s + 1] = hn;
                hown = hn;
                cur ^= 1;
                __syncthreads();
                int t = 32 * tg + 4 * m + j;        // serial step
                int col = REV ? 223 - t : t;        // native column
                yp[(size_t)col * 224 + s] = hn;     // transposed, coalesced
            }
        }

        if (tg + 2 < HGRP) fill(st, tg + 2);
        else cpa_commit();
    }
}

__global__ void __launch_bounds__(224) scan_h_kernel(
    const float* __restrict__ gates) {
    extern __shared__ __align__(128) char hsm[];
    float(*hbuf)[226] = (float(*)[226])(hsm + NSH * HSTAGEB);

    int s = threadIdx.x;
    int plane = blockIdx.x;
    int dh = blockIdx.y;  // 0 -> d0 (fwd), 1 -> d3 (rev)
    int b = plane >> 5, c = plane & 31;
    int grp0 = dh ? 9 : 0;

    const float* g1 = gates + ((size_t)(b * 384 + (grp0 + 0) * 32 + c)) * HW;
    const float* g2 = gates + ((size_t)(b * 384 + (grp0 + 1) * 32 + c)) * HW;
    const float* g3 = gates + ((size_t)(b * 384 + (grp0 + 2) * 32 + c)) * HW;
    const float* xp = g_x + (size_t)plane * HW;
    float* yp = g_dir + (size_t)(dh ? 3 : 0) * NTOT + (size_t)plane * HW;

    hbuf[0][s + 1] = 0.0f;
    if (s < 2) { hbuf[0][s * 225] = 0.0f; hbuf[1][s * 225] = 0.0f; }
    __syncthreads();

    if (dh) scan_h_body<true>(g1, g2, g3, xp, yp, hsm, hbuf, s);
    else    scan_h_body<false>(g1, g2, g3, xp, yp, hsm, hbuf, s);
}

// ---------------------------------------------------------------------------
// Combine: max over 4 direction buffers; d0,d3 stored transposed. Tiled.
// ---------------------------------------------------------------------------
__global__ void combine_t_kernel() {
    __shared__ float t0[32][33], t3[32][33];
    int plane = blockIdx.z;
    const float* p0t = g_dir + 0 * NTOT + (size_t)plane * HW;
    const float* p1 = g_dir + 1 * NTOT + (size_t)plane * HW;
    const float* p2 = g_dir + 2 * NTOT + (size_t)plane * HW;
    const float* p3t = g_dir + 3 * NTOT + (size_t)plane * HW;
    int x0 = blockIdx.x * 32, y0 = blockIdx.y * 32;
    int tx = threadIdx.x;

#pragma unroll
    for (int dy = threadIdx.y; dy < 32; dy += 8) {
        t0[dy][tx] = p0t[(x0 + dy) * HH + y0 + tx];
        t3[dy][tx] = p3t[(x0 + dy) * HH + y0 + tx];
    }
    __syncthreads();
#pragma unroll
    for (int dy = threadIdx.y; dy < 32; dy += 8) {
        float v1 = p1[(y0 + dy) * WW + x0 + tx];
        float v2 = p2[(y0 + dy) * WW + x0 + tx];
        float v0 = t0[tx][dy];
        float v3 = t3[tx][dy];
        g_x[(size_t)plane * HW + (y0 + dy) * WW + x0 + tx] =
            fmaxf(fmaxf(v0, v3), fmaxf(v1, v2));
    }
}

// ---------------------------------------------------------------------------
// K3: conv2d 3x3 same 32 -> 2 on g_x, fused log_softmax over the 2 channels.
// ---------------------------------------------------------------------------
__global__ void conv_out_kernel(const float* __restrict__ w4,
                                float* __restrict__ out) {
    __shared__ float ws[576];
    for (int i = threadIdx.x; i < 576; i += blockDim.x) ws[i] = w4[i];
    __syncthreads();

    int idx = blockIdx.x * blockDim.x + threadIdx.x;
    if (idx >= BB * HW) return;
    int b = idx / HW, pix = idx - b * HW;
    int py = pix / WW, px = pix - py * WW;

    float a0 = 0.0f, a1 = 0.0f;
    for (int ic = 0; ic < 32; ic++) {
        const float* ip = g_x + ((size_t)(b * 32 + ic)) * HW;
#pragma unroll
        for (int ky = 0; ky < 3; ky++) {
            int yy = py + ky - 1;
            bool vy = (unsigned)yy < HH;
#pragma unroll
            for (int kx = 0; kx < 3; kx++) {
                int xx = px + kx - 1;
                float v = (vy && (unsigned)xx < WW)
                              ? __ldg(ip + yy * WW + xx)
                              : 0.0f;
                int wi = ic * 9 + ky * 3 + kx;
                a0 += v * ws[wi];
                a1 += v * ws[288 + wi];
            }
        }
    }
    float mx = fmaxf(a0, a1);
    float l = mx + logf(expf(a0 - mx) + expf(a1 - mx));
    out[(size_t)(b * 2) * HW + pix] = a0 - l;
    out[(size_t)(b * 2 + 1) * HW + pix] = a1 - l;
}

// ---------------------------------------------------------------------------
// Launch: conv_in -> scan_v + scan_h -> combine -> scan_v + scan_h ->
//         combine -> conv_out.  No transposes needed.
// ---------------------------------------------------------------------------
extern "C" void kernel_launch(void* const* d_in, const int* in_sizes, int n_in,
                              void* d_out, int out_size) {
    const float* gates = (const float*)d_in[0];
    const float* y     = (const float*)d_in[1];
    const float* w3    = (const float*)d_in[2];
    const float* w4    = (const float*)d_in[3];
    float* out = (float*)d_out;

    cudaFuncSetAttribute(scan_h_kernel,
                         cudaFuncAttributeMaxDynamicSharedMemorySize, HSMEM);

    int pxblocks = (BB * HW + 255) / 256;
    dim3 sg(NPLANE, 2);
    dim3 tb(32, 8);
    dim3 cg(7, 7, NPLANE);

    conv_in_kernel<<<pxblocks, 256>>>(y, w3);
    scan_v_kernel<<<sg, 224>>>(gates);
    scan_h_kernel<<<sg, 224, HSMEM>>>(gates);
    combine_t_kernel<<<cg, tb>>>();
    scan_v_kernel<<<sg, 224>>>(gates);
    scan_h_kernel<<<sg, 224, HSMEM>>>(gates);
    combine_t_kernel<<<cg, tb>>>();
    conv_out_kernel<<<pxblocks, 256>>>(w4, out);
}